// round 2
// baseline (speedup 1.0000x reference)
#include <cuda_runtime.h>

// Problem constants
// B=8, NQ=1024, NP=2048, C=1024, H=16, D=64

// ---------------- scratch (static device globals; no runtime allocation) ----
__device__ float g_Q [8 * 1024 * 1024];   // (B, NQ, C)  32 MB
__device__ float g_K [8 * 2048 * 1024];   // (B, NP, C)  64 MB
__device__ float g_V [8 * 2048 * 1024];   // (B, NP, C)  64 MB
__device__ float g_AO[8 * 1024 * 1024];   // (B, NQ, C)  32 MB

// ---------------------------------------------------------------------------
// GEMM: Out[M,N] = A[M,K] * W[N,K]^T + bias[N]     (all fp32, K-contiguous)
// 128x128 block tile, BK=16, 256 threads, 8x8 per-thread microtile.
// M, N, K all multiples of 128/16 for this problem -> no bounds checks.
// ---------------------------------------------------------------------------
__global__ __launch_bounds__(256) void gemm_nt_bias(
    const float* __restrict__ A, const float* __restrict__ W,
    const float* __restrict__ bias, float* __restrict__ Out,
    int M, int N, int K)
{
    __shared__ float As[16][128];   // [k][m]
    __shared__ float Bs[16][128];   // [k][n]

    const int tid = threadIdx.x;
    const int tx  = tid & 15;       // column group (N)
    const int ty  = tid >> 4;       // row group (M)
    const int m0  = blockIdx.y << 7;
    const int n0  = blockIdx.x << 7;

    float acc[8][8];
#pragma unroll
    for (int i = 0; i < 8; i++)
#pragma unroll
        for (int j = 0; j < 8; j++) acc[i][j] = 0.f;

    for (int k0 = 0; k0 < K; k0 += 16) {
        // Front-batch all four global loads (2 per operand) before any STS so
        // the memory latencies overlap (MLP=4), then store to smem.
        float4 va[2], vb[2];
#pragma unroll
        for (int p = 0; p < 2; p++) {
            int id = tid + p * 256;          // 0..511 : 512 float4 per operand
            int r  = id >> 2;                // tile row 0..127
            int c  = (id & 3) << 2;          // k offset 0,4,8,12
            va[p] = *(const float4*)(A + (size_t)(m0 + r) * K + k0 + c);
            vb[p] = *(const float4*)(W + (size_t)(n0 + r) * K + k0 + c);
        }
#pragma unroll
        for (int p = 0; p < 2; p++) {
            int id = tid + p * 256;
            int r  = id >> 2;
            int c  = (id & 3) << 2;
            As[c + 0][r] = va[p].x; As[c + 1][r] = va[p].y;
            As[c + 2][r] = va[p].z; As[c + 3][r] = va[p].w;
            Bs[c + 0][r] = vb[p].x; Bs[c + 1][r] = vb[p].y;
            Bs[c + 2][r] = vb[p].z; Bs[c + 3][r] = vb[p].w;
        }
        __syncthreads();

#pragma unroll
        for (int k = 0; k < 16; k++) {
            float a[8], b[8];
            *(float4*)&a[0] = *(const float4*)&As[k][ty * 8];
            *(float4*)&a[4] = *(const float4*)&As[k][ty * 8 + 4];
            *(float4*)&b[0] = *(const float4*)&Bs[k][tx * 8];
            *(float4*)&b[4] = *(const float4*)&Bs[k][tx * 8 + 4];
#pragma unroll
            for (int i = 0; i < 8; i++)
#pragma unroll
                for (int j = 0; j < 8; j++)
                    acc[i][j] = fmaf(a[i], b[j], acc[i][j]);
        }
        __syncthreads();
    }

#pragma unroll
    for (int i = 0; i < 8; i++) {
        int row = m0 + ty * 8 + i;
#pragma unroll
        for (int j4 = 0; j4 < 8; j4 += 4) {
            int col = n0 + tx * 8 + j4;
            float4 o;
            o.x = acc[i][j4 + 0] + bias[col + 0];
            o.y = acc[i][j4 + 1] + bias[col + 1];
            o.z = acc[i][j4 + 2] + bias[col + 2];
            o.w = acc[i][j4 + 3] + bias[col + 3];
            *(float4*)(Out + (size_t)row * N + col) = o;
        }
    }
}

// ---------------------------------------------------------------------------
// RoPE applied in-place to K. One thread per (b, n, h, pair).
// total = 8*2048*16*32 = 8388608 threads. idx bits: [i:5][h:4][n:11][b:3]
// ---------------------------------------------------------------------------
__global__ void rope_k_kernel(float* __restrict__ Kb, const float* __restrict__ freqs)
{
    int idx = blockIdx.x * blockDim.x + threadIdx.x;
    int i = idx & 31;
    int h = (idx >> 5) & 15;
    int n = (idx >> 9) & 2047;
    int b = idx >> 20;
    int off = ((b * 2048 + n) << 10) + h * 64 + 2 * i;
    float2 kv = *(float2*)(Kb + off);
    float2 f  = *(const float2*)(freqs + (n * 32 + i) * 2);
    float2 o;
    o.x = kv.x * f.x - kv.y * f.y;
    o.y = kv.x * f.y + kv.y * f.x;
    *(float2*)(Kb + off) = o;
}

// ---------------------------------------------------------------------------
// Flash attention (fp32). Block = (q-tile of 64, head, batch), 256 threads.
// K-tile = 64. Thread layout 16x16: thread owns S/O microtile of 4 rows (q)
// x 4 cols. Row-softmax reduced over the 16 lanes sharing a row (shfl w=16).
// smem (dynamic, 67584 B):
//   Qs[64][64]  d-major  (Qs[d*64+q])
//   Ks[64][68]  d-major  (Ks[d*68+k])    pad 68 for store conflicts
//   Vs[64][64]  j-major  (Vs[j*64+d])
//   Ps[64][68]  j-major  (Ps[j*68+q])    pad 68
// ---------------------------------------------------------------------------
__global__ __launch_bounds__(256, 3) void flash_attn(
    const float* __restrict__ Q, const float* __restrict__ Kb,
    const float* __restrict__ V, float* __restrict__ O)
{
    extern __shared__ float sm[];
    float* Qs = sm;                 // 4096
    float* Ks = Qs + 64 * 64;       // 4352
    float* Vs = Ks + 64 * 68;       // 4096
    float* Ps = Vs + 64 * 64;       // 4352

    const int b  = blockIdx.z;
    const int h  = blockIdx.y;
    const int q0 = blockIdx.x * 64;
    const int tid = threadIdx.x;
    const int tx = tid & 15;        // cols
    const int ty = tid >> 4;        // rows

    // load Q tile transposed (d-major)
    for (int i = tid; i < 64 * 64; i += 256) {
        int d = i & 63, q = i >> 6;
        Qs[d * 64 + q] = Q[(size_t)((b * 1024 + q0 + q)) * 1024 + h * 64 + d];
    }

    float m_i[4], l_i[4], o_acc[4][4];
#pragma unroll
    for (int i = 0; i < 4; i++) {
        m_i[i] = -1e30f; l_i[i] = 0.f;
#pragma unroll
        for (int j = 0; j < 4; j++) o_acc[i][j] = 0.f;
    }

    const float scale = 0.125f;     // 1/sqrt(64)

    for (int k0 = 0; k0 < 2048; k0 += 64) {
        __syncthreads();            // previous iter done with Ks/Vs/Ps, Qs ready
        // load K transposed, V straight
        for (int i = tid; i < 64 * 64; i += 256) {
            int d = i & 63, kk = i >> 6;
            Ks[d * 68 + kk] = Kb[(size_t)((b * 2048 + k0 + kk)) * 1024 + h * 64 + d];
        }
        for (int i = tid; i < 64 * 16; i += 256) {
            int c4 = (i & 15) << 2, j = i >> 4;
            *(float4*)&Vs[j * 64 + c4] =
                *(const float4*)(V + (size_t)((b * 2048 + k0 + j)) * 1024 + h * 64 + c4);
        }
        __syncthreads();

        // S = Q * K^T  (64x64x64 mini-GEMM)
        float s[4][4];
#pragma unroll
        for (int i = 0; i < 4; i++)
#pragma unroll
            for (int j = 0; j < 4; j++) s[i][j] = 0.f;

#pragma unroll 8
        for (int d = 0; d < 64; d++) {
            float4 a  = *(const float4*)&Qs[d * 64 + ty * 4];
            float4 bb = *(const float4*)&Ks[d * 68 + tx * 4];
            s[0][0] = fmaf(a.x, bb.x, s[0][0]); s[0][1] = fmaf(a.x, bb.y, s[0][1]);
            s[0][2] = fmaf(a.x, bb.z, s[0][2]); s[0][3] = fmaf(a.x, bb.w, s[0][3]);
            s[1][0] = fmaf(a.y, bb.x, s[1][0]); s[1][1] = fmaf(a.y, bb.y, s[1][1]);
            s[1][2] = fmaf(a.y, bb.z, s[1][2]); s[1][3] = fmaf(a.y, bb.w, s[1][3]);
            s[2][0] = fmaf(a.z, bb.x, s[2][0]); s[2][1] = fmaf(a.z, bb.y, s[2][1]);
            s[2][2] = fmaf(a.z, bb.z, s[2][2]); s[2][3] = fmaf(a.z, bb.w, s[2][3]);
            s[3][0] = fmaf(a.w, bb.x, s[3][0]); s[3][1] = fmaf(a.w, bb.y, s[3][1]);
            s[3][2] = fmaf(a.w, bb.z, s[3][2]); s[3][3] = fmaf(a.w, bb.w, s[3][3]);
        }

        // online softmax per row (row group = 16 lanes with same ty)
#pragma unroll
        for (int i = 0; i < 4; i++) {
            float r = -1e30f;
#pragma unroll
            for (int j = 0; j < 4; j++) { s[i][j] *= scale; r = fmaxf(r, s[i][j]); }
            r = fmaxf(r, __shfl_xor_sync(0xffffffffu, r, 1, 16));
            r = fmaxf(r, __shfl_xor_sync(0xffffffffu, r, 2, 16));
            r = fmaxf(r, __shfl_xor_sync(0xffffffffu, r, 4, 16));
            r = fmaxf(r, __shfl_xor_sync(0xffffffffu, r, 8, 16));
            float mnew  = fmaxf(m_i[i], r);
            float alpha = __expf(m_i[i] - mnew);
            m_i[i] = mnew;
            float ps = 0.f;
#pragma unroll
            for (int j = 0; j < 4; j++) {
                float p = __expf(s[i][j] - mnew);
                s[i][j] = p; ps += p;
            }
            ps += __shfl_xor_sync(0xffffffffu, ps, 1, 16);
            ps += __shfl_xor_sync(0xffffffffu, ps, 2, 16);
            ps += __shfl_xor_sync(0xffffffffu, ps, 4, 16);
            ps += __shfl_xor_sync(0xffffffffu, ps, 8, 16);
            l_i[i] = l_i[i] * alpha + ps;
#pragma unroll
            for (int j = 0; j < 4; j++) o_acc[i][j] *= alpha;
        }

        // store P transposed (j-major)
#pragma unroll
        for (int j = 0; j < 4; j++)
#pragma unroll
            for (int i = 0; i < 4; i++)
                Ps[(tx * 4 + j) * 68 + ty * 4 + i] = s[i][j];
        __syncthreads();

        // O += P * V  (64x64x64 mini-GEMM, inner dim = j)
#pragma unroll 8
        for (int j = 0; j < 64; j++) {
            float4 a  = *(const float4*)&Ps[j * 68 + ty * 4];
            float4 bb = *(const float4*)&Vs[j * 64 + tx * 4];
            o_acc[0][0] = fmaf(a.x, bb.x, o_acc[0][0]); o_acc[0][1] = fmaf(a.x, bb.y, o_acc[0][1]);
            o_acc[0][2] = fmaf(a.x, bb.z, o_acc[0][2]); o_acc[0][3] = fmaf(a.x, bb.w, o_acc[0][3]);
            o_acc[1][0] = fmaf(a.y, bb.x, o_acc[1][0]); o_acc[1][1] = fmaf(a.y, bb.y, o_acc[1][1]);
            o_acc[1][2] = fmaf(a.y, bb.z, o_acc[1][2]); o_acc[1][3] = fmaf(a.y, bb.w, o_acc[1][3]);
            o_acc[2][0] = fmaf(a.z, bb.x, o_acc[2][0]); o_acc[2][1] = fmaf(a.z, bb.y, o_acc[2][1]);
            o_acc[2][2] = fmaf(a.z, bb.z, o_acc[2][2]); o_acc[2][3] = fmaf(a.z, bb.w, o_acc[2][3]);
            o_acc[3][0] = fmaf(a.w, bb.x, o_acc[3][0]); o_acc[3][1] = fmaf(a.w, bb.y, o_acc[3][1]);
            o_acc[3][2] = fmaf(a.w, bb.z, o_acc[3][2]); o_acc[3][3] = fmaf(a.w, bb.w, o_acc[3][3]);
        }
    }

    // epilogue: normalize and store
#pragma unroll
    for (int i = 0; i < 4; i++) {
        float inv = 1.f / l_i[i];
        int row = b * 1024 + q0 + ty * 4 + i;
        float4 o;
        o.x = o_acc[i][0] * inv; o.y = o_acc[i][1] * inv;
        o.z = o_acc[i][2] * inv; o.w = o_acc[i][3] * inv;
        *(float4*)(O + (size_t)row * 1024 + h * 64 + tx * 4) = o;
    }
}

// ---------------------------------------------------------------------------
extern "C" void kernel_launch(void* const* d_in, const int* in_sizes, int n_in,
                              void* d_out, int out_size)
{
    const float* x     = (const float*)d_in[0];
    const float* ctx   = (const float*)d_in[1];
    const float* freqs = (const float*)d_in[2];
    const float* wq    = (const float*)d_in[3];
    const float* bq    = (const float*)d_in[4];
    const float* wk    = (const float*)d_in[5];
    const float* bk    = (const float*)d_in[6];
    const float* wv    = (const float*)d_in[7];
    const float* bv    = (const float*)d_in[8];
    const float* wo    = (const float*)d_in[9];
    const float* bo    = (const float*)d_in[10];
    float* out = (float*)d_out;

    float *pQ, *pK, *pV, *pAO;
    cudaGetSymbolAddress((void**)&pQ,  g_Q);
    cudaGetSymbolAddress((void**)&pK,  g_K);
    cudaGetSymbolAddress((void**)&pV,  g_V);
    cudaGetSymbolAddress((void**)&pAO, g_AO);

    const int FLASH_SMEM = (64 * 64 + 64 * 68 + 64 * 64 + 64 * 68) * 4; // 67584
    cudaFuncSetAttribute(flash_attn, cudaFuncAttributeMaxDynamicSharedMemorySize, FLASH_SMEM);

    // Projections: Q, K, V
    gemm_nt_bias<<<dim3(8,  64), 256>>>(x,   wq, bq, pQ,  8192, 1024, 1024);
    gemm_nt_bias<<<dim3(8, 128), 256>>>(ctx, wk, bk, pK, 16384, 1024, 1024);
    gemm_nt_bias<<<dim3(8, 128), 256>>>(ctx, wv, bv, pV, 16384, 1024, 1024);

    // RoPE on K (in place)
    rope_k_kernel<<<8388608 / 256, 256>>>(pK, freqs);

    // Attention
    flash_attn<<<dim3(16, 16, 8), 256, FLASH_SMEM>>>(pQ, pK, pV, pAO);

    // Output projection straight into d_out
    gemm_nt_bias<<<dim3(8, 64), 256>>>(pAO, wo, bo, out, 8192, 1024, 1024);
}

// round 3
// speedup vs baseline: 2.4118x; 2.4118x over previous
#include <cuda_runtime.h>
#include <cuda_bf16.h>
#include <cstdint>

// Problem constants: B=8, NQ=1024, NP=2048, C=1024, H=16, D=64

// ---------------- scratch (static device globals; no runtime allocation) ----
__device__ float g_Q [8 * 1024 * 1024];   // (B, NQ, C)
__device__ float g_K [8 * 2048 * 1024];   // (B, NP, C)
__device__ float g_V [8 * 2048 * 1024];   // (B, NP, C)
__device__ float g_AO[8 * 1024 * 1024];   // (B, NQ, C)

// ---------------------------------------------------------------------------
// helpers
// ---------------------------------------------------------------------------
static __device__ __forceinline__ uint32_t smaddr(const void* p) {
    return (uint32_t)__cvta_generic_to_shared(p);
}

static __device__ __forceinline__ void ldsm4(uint32_t r[4], uint32_t addr) {
    asm volatile("ldmatrix.sync.aligned.m8n8.x4.shared.b16 {%0,%1,%2,%3}, [%4];\n"
                 : "=r"(r[0]), "=r"(r[1]), "=r"(r[2]), "=r"(r[3]) : "r"(addr));
}

static __device__ __forceinline__ void ldsm4t(uint32_t r[4], uint32_t addr) {
    asm volatile("ldmatrix.sync.aligned.m8n8.x4.trans.shared.b16 {%0,%1,%2,%3}, [%4];\n"
                 : "=r"(r[0]), "=r"(r[1]), "=r"(r[2]), "=r"(r[3]) : "r"(addr));
}

static __device__ __forceinline__ void mma16816(float c[4], const uint32_t a[4],
                                                uint32_t b0, uint32_t b1) {
    asm volatile(
        "mma.sync.aligned.m16n8k16.row.col.f32.bf16.bf16.f32 "
        "{%0,%1,%2,%3},{%4,%5,%6,%7},{%8,%9},{%0,%1,%2,%3};\n"
        : "+f"(c[0]), "+f"(c[1]), "+f"(c[2]), "+f"(c[3])
        : "r"(a[0]), "r"(a[1]), "r"(a[2]), "r"(a[3]), "r"(b0), "r"(b1));
}

// split fp32 -> (hi, lo) bf16 and store 4 consecutive elements
static __device__ __forceinline__ void splitst(__nv_bfloat16* hp, __nv_bfloat16* lp, float4 v) {
    float f[4] = {v.x, v.y, v.z, v.w};
    __nv_bfloat16 h[4], l[4];
#pragma unroll
    for (int i = 0; i < 4; i++) {
        h[i] = __float2bfloat16(f[i]);
        l[i] = __float2bfloat16(f[i] - __bfloat162float(h[i]));
    }
    *reinterpret_cast<__nv_bfloat162*>(hp)     = __nv_bfloat162(h[0], h[1]);
    *reinterpret_cast<__nv_bfloat162*>(hp + 2) = __nv_bfloat162(h[2], h[3]);
    *reinterpret_cast<__nv_bfloat162*>(lp)     = __nv_bfloat162(l[0], l[1]);
    *reinterpret_cast<__nv_bfloat162*>(lp + 2) = __nv_bfloat162(l[2], l[3]);
}

static __device__ __forceinline__ void split_pack(float x, float y, uint32_t& hi, uint32_t& lo) {
    __nv_bfloat16 hx = __float2bfloat16(x), hy = __float2bfloat16(y);
    __nv_bfloat16 lx = __float2bfloat16(x - __bfloat162float(hx));
    __nv_bfloat16 ly = __float2bfloat16(y - __bfloat162float(hy));
    __nv_bfloat162 H(hx, hy), L(lx, ly);
    hi = *reinterpret_cast<uint32_t*>(&H);
    lo = *reinterpret_cast<uint32_t*>(&L);
}

// ---------------------------------------------------------------------------
// Split-bf16 GEMM: Out[M,N] = A[M,K] * W[N,K]^T + bias   (fp32 in/out)
// 128x128 block, 8 warps (32x64 each), BK=32, 3-pass hi/lo mma.
// ---------------------------------------------------------------------------
__global__ __launch_bounds__(256) void gemm_bf16x3(
    const float* __restrict__ A, const float* __restrict__ W,
    const float* __restrict__ bias, float* __restrict__ Out,
    int M, int N, int K)
{
    __shared__ __nv_bfloat16 Ah[128 * 40], Al[128 * 40];
    __shared__ __nv_bfloat16 Bh[128 * 40], Bl[128 * 40];

    const int tid = threadIdx.x;
    const int lane = tid & 31, wid = tid >> 5;
    const int wm = wid & 3, wn = wid >> 2;
    const int m0 = blockIdx.y << 7, n0 = blockIdx.x << 7;

    float acc[2][8][4];
#pragma unroll
    for (int i = 0; i < 2; i++)
#pragma unroll
        for (int j = 0; j < 8; j++)
#pragma unroll
            for (int t = 0; t < 4; t++) acc[i][j][t] = 0.f;

    float4 va[4], vb[4];

#define LOADG(K0) do {                                                         \
    _Pragma("unroll")                                                          \
    for (int p = 0; p < 4; p++) {                                              \
        int idx = tid + p * 256; int r = idx >> 3; int c = (idx & 7) << 2;     \
        va[p] = *(const float4*)(A + (size_t)(m0 + r) * K + (K0) + c);         \
        vb[p] = *(const float4*)(W + (size_t)(n0 + r) * K + (K0) + c);         \
    } } while (0)

#define STORES() do {                                                          \
    _Pragma("unroll")                                                          \
    for (int p = 0; p < 4; p++) {                                              \
        int idx = tid + p * 256; int r = idx >> 3; int c = (idx & 7) << 2;     \
        splitst(&Ah[r * 40 + c], &Al[r * 40 + c], va[p]);                      \
        splitst(&Bh[r * 40 + c], &Bl[r * 40 + c], vb[p]);                      \
    } } while (0)

    LOADG(0); STORES();
    __syncthreads();

    for (int k0 = 0; k0 < K; k0 += 32) {
        bool more = (k0 + 32) < K;
        if (more) LOADG(k0 + 32);

#pragma unroll
        for (int s = 0; s < 2; s++) {
            uint32_t ah[2][4], al[2][4];
#pragma unroll
            for (int mi = 0; mi < 2; mi++) {
                int row = wm * 32 + mi * 16 + (lane & 7) + 8 * ((lane >> 3) & 1);
                int col = s * 16 + 8 * (lane >> 4);
                ldsm4(ah[mi], smaddr(&Ah[row * 40 + col]));
                ldsm4(al[mi], smaddr(&Al[row * 40 + col]));
            }
#pragma unroll
            for (int ng = 0; ng < 4; ng++) {
                uint32_t bh[4], bl[4];
                int row = wn * 64 + ng * 16 + (lane & 7) + 8 * (lane >> 4);
                int col = s * 16 + 8 * ((lane >> 3) & 1);
                ldsm4(bh, smaddr(&Bh[row * 40 + col]));
                ldsm4(bl, smaddr(&Bl[row * 40 + col]));
#pragma unroll
                for (int mi = 0; mi < 2; mi++) {
                    mma16816(acc[mi][2 * ng],     ah[mi], bh[0], bh[1]);
                    mma16816(acc[mi][2 * ng],     ah[mi], bl[0], bl[1]);
                    mma16816(acc[mi][2 * ng],     al[mi], bh[0], bh[1]);
                    mma16816(acc[mi][2 * ng + 1], ah[mi], bh[2], bh[3]);
                    mma16816(acc[mi][2 * ng + 1], ah[mi], bl[2], bl[3]);
                    mma16816(acc[mi][2 * ng + 1], al[mi], bh[2], bh[3]);
                }
            }
        }
        __syncthreads();
        if (more) { STORES(); __syncthreads(); }
    }

#pragma unroll
    for (int mi = 0; mi < 2; mi++)
#pragma unroll
        for (int nj = 0; nj < 8; nj++) {
            int row = m0 + wm * 32 + mi * 16 + (lane >> 2);
            int col = n0 + wn * 64 + nj * 8 + (lane & 3) * 2;
            float2 bz = *(const float2*)(bias + col);
            float2 o0 = {acc[mi][nj][0] + bz.x, acc[mi][nj][1] + bz.y};
            float2 o1 = {acc[mi][nj][2] + bz.x, acc[mi][nj][3] + bz.y};
            *(float2*)(Out + (size_t)row * N + col)       = o0;
            *(float2*)(Out + (size_t)(row + 8) * N + col) = o1;
        }
#undef LOADG
#undef STORES
}

// ---------------------------------------------------------------------------
// RoPE applied in-place to K (fp32).
// ---------------------------------------------------------------------------
__global__ void rope_k_kernel(float* __restrict__ Kb, const float* __restrict__ freqs)
{
    int idx = blockIdx.x * blockDim.x + threadIdx.x;
    int i = idx & 31;
    int h = (idx >> 5) & 15;
    int n = (idx >> 9) & 2047;
    int b = idx >> 20;
    int off = ((b * 2048 + n) << 10) + h * 64 + 2 * i;
    float2 kv = *(float2*)(Kb + off);
    float2 f  = *(const float2*)(freqs + (n * 32 + i) * 2);
    float2 o;
    o.x = kv.x * f.x - kv.y * f.y;
    o.y = kv.x * f.y + kv.y * f.x;
    *(float2*)(Kb + off) = o;
}

// ---------------------------------------------------------------------------
// Flash attention, split-bf16 tensor cores.
// Block: 128 thr (4 warps), q-tile 64 (warp owns 16 q rows), key-tile 64.
// Ks/Vs: [kk][d] hi/lo bf16, row stride 72 (LDSM conflict-free, 16B aligned).
// Q fragments persist in registers. P converted S-frag->A-frag in registers.
// V consumed via ldmatrix.trans (B col-major for PV).
// ---------------------------------------------------------------------------
__global__ __launch_bounds__(128) void flash_attn_bf16(
    const float* __restrict__ Q, const float* __restrict__ Kg,
    const float* __restrict__ Vg, float* __restrict__ Og)
{
    __shared__ __nv_bfloat16 Ksh[64 * 72], Ksl[64 * 72];
    __shared__ __nv_bfloat16 Vsh[64 * 72], Vsl[64 * 72];

    const int tid = threadIdx.x;
    const int lane = tid & 31, wid = tid >> 5;
    const int b = blockIdx.z, h = blockIdx.y;
    const int q0 = blockIdx.x * 64;

    // stage Q (hi/lo) into Ks buffers, then lift fragments to registers
#pragma unroll
    for (int p = 0; p < 8; p++) {
        int idx = tid + p * 128;
        int q = idx >> 4, d = (idx & 15) << 2;
        float4 v = *(const float4*)(Q + (size_t)(b * 1024 + q0 + q) * 1024 + h * 64 + d);
        splitst(&Ksh[q * 72 + d], &Ksl[q * 72 + d], v);
    }
    __syncthreads();

    uint32_t qh[4][4], ql[4][4];
#pragma unroll
    for (int s = 0; s < 4; s++) {
        int row = wid * 16 + (lane & 7) + 8 * ((lane >> 3) & 1);
        int col = s * 16 + 8 * (lane >> 4);
        ldsm4(qh[s], smaddr(&Ksh[row * 72 + col]));
        ldsm4(ql[s], smaddr(&Ksl[row * 72 + col]));
    }
    __syncthreads();

    float oacc[8][4];
#pragma unroll
    for (int j = 0; j < 8; j++)
#pragma unroll
        for (int t = 0; t < 4; t++) oacc[j][t] = 0.f;
    float mrow0 = -1e30f, mrow1 = -1e30f, lrow0 = 0.f, lrow1 = 0.f;

    for (int kb = 0; kb < 2048; kb += 64) {
        // stage K and V tiles (hi/lo split)
#pragma unroll
        for (int p = 0; p < 8; p++) {
            int idx = tid + p * 128;
            int kk = idx >> 4, d = (idx & 15) << 2;
            size_t goff = (size_t)(b * 2048 + kb + kk) * 1024 + h * 64 + d;
            float4 kv = *(const float4*)(Kg + goff);
            float4 vv = *(const float4*)(Vg + goff);
            splitst(&Ksh[kk * 72 + d], &Ksl[kk * 72 + d], kv);
            splitst(&Vsh[kk * 72 + d], &Vsl[kk * 72 + d], vv);
        }
        __syncthreads();

        // S = Q K^T  (16 q-rows x 64 keys per warp)
        float sfr[8][4];
#pragma unroll
        for (int j = 0; j < 8; j++)
#pragma unroll
            for (int t = 0; t < 4; t++) sfr[j][t] = 0.f;

#pragma unroll
        for (int s = 0; s < 4; s++) {
#pragma unroll
            for (int ng = 0; ng < 4; ng++) {
                uint32_t bh[4], bl[4];
                int row = ng * 16 + (lane & 7) + 8 * (lane >> 4);
                int col = s * 16 + 8 * ((lane >> 3) & 1);
                ldsm4(bh, smaddr(&Ksh[row * 72 + col]));
                ldsm4(bl, smaddr(&Ksl[row * 72 + col]));
                mma16816(sfr[2 * ng],     qh[s], bh[0], bh[1]);
                mma16816(sfr[2 * ng],     qh[s], bl[0], bl[1]);
                mma16816(sfr[2 * ng],     ql[s], bh[0], bh[1]);
                mma16816(sfr[2 * ng + 1], qh[s], bh[2], bh[3]);
                mma16816(sfr[2 * ng + 1], qh[s], bl[2], bl[3]);
                mma16816(sfr[2 * ng + 1], ql[s], bh[2], bh[3]);
            }
        }

        // online softmax (rows g=lane>>2 and g+8; 4 lanes share a row)
        const float sc = 0.125f;
        float rm0 = -1e30f, rm1 = -1e30f;
#pragma unroll
        for (int j = 0; j < 8; j++) {
            sfr[j][0] *= sc; sfr[j][1] *= sc; sfr[j][2] *= sc; sfr[j][3] *= sc;
            rm0 = fmaxf(rm0, fmaxf(sfr[j][0], sfr[j][1]));
            rm1 = fmaxf(rm1, fmaxf(sfr[j][2], sfr[j][3]));
        }
        rm0 = fmaxf(rm0, __shfl_xor_sync(0xffffffffu, rm0, 1, 4));
        rm0 = fmaxf(rm0, __shfl_xor_sync(0xffffffffu, rm0, 2, 4));
        rm1 = fmaxf(rm1, __shfl_xor_sync(0xffffffffu, rm1, 1, 4));
        rm1 = fmaxf(rm1, __shfl_xor_sync(0xffffffffu, rm1, 2, 4));

        float mn0 = fmaxf(mrow0, rm0), mn1 = fmaxf(mrow1, rm1);
        float al0 = __expf(mrow0 - mn0), al1 = __expf(mrow1 - mn1);
        mrow0 = mn0; mrow1 = mn1;

        float ps0 = 0.f, ps1 = 0.f;
#pragma unroll
        for (int j = 0; j < 8; j++) {
            sfr[j][0] = __expf(sfr[j][0] - mn0); ps0 += sfr[j][0];
            sfr[j][1] = __expf(sfr[j][1] - mn0); ps0 += sfr[j][1];
            sfr[j][2] = __expf(sfr[j][2] - mn1); ps1 += sfr[j][2];
            sfr[j][3] = __expf(sfr[j][3] - mn1); ps1 += sfr[j][3];
        }
        ps0 += __shfl_xor_sync(0xffffffffu, ps0, 1, 4);
        ps0 += __shfl_xor_sync(0xffffffffu, ps0, 2, 4);
        ps1 += __shfl_xor_sync(0xffffffffu, ps1, 1, 4);
        ps1 += __shfl_xor_sync(0xffffffffu, ps1, 2, 4);
        lrow0 = lrow0 * al0 + ps0;
        lrow1 = lrow1 * al1 + ps1;
#pragma unroll
        for (int j = 0; j < 8; j++) {
            oacc[j][0] *= al0; oacc[j][1] *= al0;
            oacc[j][2] *= al1; oacc[j][3] *= al1;
        }

        // convert P (S-frags) -> A-frags, hi/lo, in registers
        uint32_t pah[4][4], pal[4][4];
#pragma unroll
        for (int c = 0; c < 4; c++) {
            split_pack(sfr[2 * c][0],     sfr[2 * c][1],     pah[c][0], pal[c][0]);
            split_pack(sfr[2 * c][2],     sfr[2 * c][3],     pah[c][1], pal[c][1]);
            split_pack(sfr[2 * c + 1][0], sfr[2 * c + 1][1], pah[c][2], pal[c][2]);
            split_pack(sfr[2 * c + 1][2], sfr[2 * c + 1][3], pah[c][3], pal[c][3]);
        }

        // O += P V   (B = V via ldmatrix.trans: col-major k x d)
#pragma unroll
        for (int c = 0; c < 4; c++) {
#pragma unroll
            for (int djp = 0; djp < 4; djp++) {
                uint32_t vbh[4], vbl[4];
                int row = c * 16 + (lane & 7) + 8 * ((lane >> 3) & 1);
                int col = djp * 16 + 8 * (lane >> 4);
                ldsm4t(vbh, smaddr(&Vsh[row * 72 + col]));
                ldsm4t(vbl, smaddr(&Vsl[row * 72 + col]));
                mma16816(oacc[2 * djp],     pah[c], vbh[0], vbh[1]);
                mma16816(oacc[2 * djp],     pah[c], vbl[0], vbl[1]);
                mma16816(oacc[2 * djp],     pal[c], vbh[0], vbh[1]);
                mma16816(oacc[2 * djp + 1], pah[c], vbh[2], vbh[3]);
                mma16816(oacc[2 * djp + 1], pah[c], vbl[2], vbl[3]);
                mma16816(oacc[2 * djp + 1], pal[c], vbh[2], vbh[3]);
            }
        }
        __syncthreads();
    }

    // epilogue
    float inv0 = 1.f / lrow0, inv1 = 1.f / lrow1;
#pragma unroll
    for (int dj = 0; dj < 8; dj++) {
        int row = q0 + wid * 16 + (lane >> 2);
        int col = h * 64 + dj * 8 + (lane & 3) * 2;
        float2 o0 = {oacc[dj][0] * inv0, oacc[dj][1] * inv0};
        float2 o1 = {oacc[dj][2] * inv1, oacc[dj][3] * inv1};
        *(float2*)(Og + (size_t)(b * 1024 + row) * 1024 + col)       = o0;
        *(float2*)(Og + (size_t)(b * 1024 + row + 8) * 1024 + col)   = o1;
    }
}

// ---------------------------------------------------------------------------
extern "C" void kernel_launch(void* const* d_in, const int* in_sizes, int n_in,
                              void* d_out, int out_size)
{
    const float* x     = (const float*)d_in[0];
    const float* ctx   = (const float*)d_in[1];
    const float* freqs = (const float*)d_in[2];
    const float* wq    = (const float*)d_in[3];
    const float* bq    = (const float*)d_in[4];
    const float* wk    = (const float*)d_in[5];
    const float* bk    = (const float*)d_in[6];
    const float* wv    = (const float*)d_in[7];
    const float* bv    = (const float*)d_in[8];
    const float* wo    = (const float*)d_in[9];
    const float* bo    = (const float*)d_in[10];
    float* out = (float*)d_out;

    float *pQ, *pK, *pV, *pAO;
    cudaGetSymbolAddress((void**)&pQ,  g_Q);
    cudaGetSymbolAddress((void**)&pK,  g_K);
    cudaGetSymbolAddress((void**)&pV,  g_V);
    cudaGetSymbolAddress((void**)&pAO, g_AO);

    // Projections (split-bf16 tensor cores)
    gemm_bf16x3<<<dim3(8,  64), 256>>>(x,   wq, bq, pQ,  8192, 1024, 1024);
    gemm_bf16x3<<<dim3(8, 128), 256>>>(ctx, wk, bk, pK, 16384, 1024, 1024);
    gemm_bf16x3<<<dim3(8, 128), 256>>>(ctx, wv, bv, pV, 16384, 1024, 1024);

    // RoPE on K (in place, fp32)
    rope_k_kernel<<<8388608 / 256, 256>>>(pK, freqs);

    // Attention (split-bf16 tensor cores)
    flash_attn_bf16<<<dim3(16, 16, 8), 128>>>(pQ, pK, pV, pAO);

    // Output projection straight into d_out
    gemm_bf16x3<<<dim3(8, 64), 256>>>(pAO, wo, bo, out, 8192, 1024, 1024);
}